// round 1
// baseline (speedup 1.0000x reference)
#include <cuda_runtime.h>
#include <cstdint>
#include <math_constants.h>

#define NN 100000
#define EE 600000
#define DD 128
#define EPSLN 1e-5f

// ---------------- scratch (device globals; allocation-free at launch) ----------
__device__ float g_y[3L * NN * DD];          // per-mixed y scratch (3,N,128); also reused for hcat
__device__ float g_hin[(size_t)NN * DD];
__device__ float g_s0[(size_t)NN * DD];
__device__ float g_s1[(size_t)NN * DD];
__device__ float g_m0[(size_t)NN * DD];
__device__ float g_m1[(size_t)NN * DD];
__device__ float g_slast[(size_t)NN * DD];
__device__ float g_mean[(size_t)NN * DD];    // agg mean  (also reused as pre1 = src-hr)
__device__ float g_max[(size_t)NN * DD];     // agg max   (also reused as pre2 = src*hr)
__device__ float g_stats[2 * 3 * DD];        // sums[3*128], sumsq[3*128]
__device__ int   g_deg[NN];
__device__ int   g_rowptr[NN + 1];
__device__ int   g_cursor[NN];               // also used as inclusive-scan temp
__device__ int   g_ssrc[EE];
__device__ int   g_bsums[256];

// ---------------- CSR build ---------------------------------------------------
__global__ void k_hist(const int* __restrict__ dst, int* deg, int e) {
    int i = blockIdx.x * blockDim.x + threadIdx.x;
    if (i < e) atomicAdd(&deg[dst[i]], 1);
}

__global__ void k_scan_block(const int* __restrict__ deg, int* incl, int* bsums, int n) {
    __shared__ int sh[1024];
    int i = blockIdx.x * 1024 + threadIdx.x;
    int v = (i < n) ? deg[i] : 0;
    sh[threadIdx.x] = v;
    __syncthreads();
    for (int off = 1; off < 1024; off <<= 1) {
        int t = (threadIdx.x >= off) ? sh[threadIdx.x - off] : 0;
        __syncthreads();
        sh[threadIdx.x] += t;
        __syncthreads();
    }
    if (i < n) incl[i] = sh[threadIdx.x];
    if (threadIdx.x == 1023) bsums[blockIdx.x] = sh[1023];
}

__global__ void k_scan_sums(int* bsums, int nb) {
    if (threadIdx.x == 0 && blockIdx.x == 0) {
        int run = 0;
        for (int i = 0; i < nb; i++) { int t = bsums[i]; bsums[i] = run; run += t; }
    }
}

__global__ void k_scan_fin(const int* __restrict__ deg, const int* __restrict__ incl,
                           const int* __restrict__ bsums, int* rowptr, int* cursor, int n, int e) {
    int i = blockIdx.x * blockDim.x + threadIdx.x;
    if (i < n) {
        int ex = incl[i] - deg[i] + bsums[i >> 10];
        rowptr[i] = ex;
        cursor[i] = ex;
        if (i == n - 1) rowptr[n] = e;
    }
}

__global__ void k_scatter(const int* __restrict__ src, const int* __restrict__ dst,
                          int* cursor, int* ssrc, int e) {
    int i = blockIdx.x * blockDim.x + threadIdx.x;
    if (i < e) {
        int p = atomicAdd(&cursor[dst[i]], 1);
        ssrc[p] = src[i];
    }
}

// ---------------- graph aggregation (mean + max), warp per node ---------------
__global__ void k_agg(const float* __restrict__ h, const int* __restrict__ rowptr,
                      const int* __restrict__ ssrc, float* __restrict__ meanout,
                      float* __restrict__ maxout, int n) {
    int warp = (blockIdx.x * blockDim.x + threadIdx.x) >> 5;
    int lane = threadIdx.x & 31;
    if (warp >= n) return;
    int beg = rowptr[warp], end = rowptr[warp + 1];
    float4 s  = make_float4(0.f, 0.f, 0.f, 0.f);
    float4 mx = make_float4(-CUDART_INF_F, -CUDART_INF_F, -CUDART_INF_F, -CUDART_INF_F);
    for (int i = beg; i < end; i++) {
        int src = ssrc[i];
        float4 v = ((const float4*)(h + (size_t)src * DD))[lane];
        s.x += v.x; s.y += v.y; s.z += v.z; s.w += v.w;
        mx.x = fmaxf(mx.x, v.x); mx.y = fmaxf(mx.y, v.y);
        mx.z = fmaxf(mx.z, v.z); mx.w = fmaxf(mx.w, v.w);
    }
    int deg = end - beg;
    float inv = 1.0f / (float)max(deg, 1);
    float4 mo = make_float4(s.x * inv, s.y * inv, s.z * inv, s.w * inv);
    float4 xo = (deg > 0) ? mx : make_float4(0.f, 0.f, 0.f, 0.f);
    ((float4*)(meanout + (size_t)warp * DD))[lane] = mo;
    ((float4*)(maxout  + (size_t)warp * DD))[lane] = xo;
}

// ---------------- elementwise pre-candidates ----------------------------------
__global__ void k_pre(const float* __restrict__ a, const float* __restrict__ b,
                      float* __restrict__ p1, float* __restrict__ p2, int total) {
    int i = blockIdx.x * blockDim.x + threadIdx.x;
    if (i < total) {
        float x = a[i], y = b[i];
        p1[i] = x - y;
        p2[i] = x * y;
    }
}

// ---------------- GEMM: y[k] = x[k] @ W[k] + b[k]  (N x 128 x 128) -------------
// BM=128, BN=128 (full), BK=8, 256 threads, 8x8 thread tile (split 4+4 layout)
__global__ void k_gemm128(const float* __restrict__ x0, const float* __restrict__ x1,
                          const float* __restrict__ x2, const float* __restrict__ W,
                          const float* __restrict__ B, float* __restrict__ Y,
                          int n, size_t ystride) {
    int k = blockIdx.z;
    const float* X  = (k == 0) ? x0 : (k == 1 ? x1 : x2);
    const float* Wk = W + (size_t)k * DD * DD;
    const float* bk = B + k * DD;
    float* Yk = Y + (size_t)k * ystride;
    int row0 = blockIdx.x * 128;

    __shared__ float Xs[8][128];
    __shared__ float Ws[8][128];
    int tid = threadIdx.x;
    int tx = tid & 15, ty = tid >> 4;
    int lrow = tid >> 1, lpart = tid & 1;   // X loads: 128 rows x 2 float4
    int wrow = tid >> 5, wcol = tid & 31;   // W loads: 8 rows x 32 float4

    float acc[8][8];
    #pragma unroll
    for (int i = 0; i < 8; i++)
        #pragma unroll
        for (int j = 0; j < 8; j++) acc[i][j] = 0.f;

    for (int kk = 0; kk < DD; kk += 8) {
        float4 xv = make_float4(0.f, 0.f, 0.f, 0.f);
        int gr = row0 + lrow;
        if (gr < n) xv = *(const float4*)(X + (size_t)gr * DD + kk + lpart * 4);
        Xs[lpart * 4 + 0][lrow] = xv.x;
        Xs[lpart * 4 + 1][lrow] = xv.y;
        Xs[lpart * 4 + 2][lrow] = xv.z;
        Xs[lpart * 4 + 3][lrow] = xv.w;
        float4 wv = *(const float4*)(Wk + (size_t)(kk + wrow) * DD + wcol * 4);
        *(float4*)&Ws[wrow][wcol * 4] = wv;
        __syncthreads();
        #pragma unroll
        for (int kb = 0; kb < 8; kb++) {
            float a[8], bb[8];
            #pragma unroll
            for (int i = 0; i < 4; i++) {
                a[i]      = Xs[kb][ty * 4 + i];
                a[4 + i]  = Xs[kb][64 + ty * 4 + i];
                bb[i]     = Ws[kb][tx * 4 + i];
                bb[4 + i] = Ws[kb][64 + tx * 4 + i];
            }
            #pragma unroll
            for (int i = 0; i < 8; i++)
                #pragma unroll
                for (int j = 0; j < 8; j++) acc[i][j] += a[i] * bb[j];
        }
        __syncthreads();
    }
    #pragma unroll
    for (int i = 0; i < 8; i++) {
        int r = row0 + ((i < 4) ? (ty * 4 + i) : (64 + ty * 4 + (i - 4)));
        if (r >= n) continue;
        #pragma unroll
        for (int jh = 0; jh < 2; jh++) {
            int c0 = jh ? (64 + tx * 4) : (tx * 4);
            float4 o;
            o.x = acc[i][jh * 4 + 0] + bk[c0 + 0];
            o.y = acc[i][jh * 4 + 1] + bk[c0 + 1];
            o.z = acc[i][jh * 4 + 2] + bk[c0 + 2];
            o.w = acc[i][jh * 4 + 3] + bk[c0 + 3];
            *(float4*)(Yk + (size_t)r * DD + c0) = o;
        }
    }
}

// ---------------- GEMM cat: hcat = [m0|m1|slast] @ W_cat + b_cat (K=384) -------
__global__ void k_gemm_cat(const float* __restrict__ m0, const float* __restrict__ m1,
                           const float* __restrict__ sl, const float* __restrict__ W,
                           const float* __restrict__ B, float* __restrict__ Y, int n) {
    int row0 = blockIdx.x * 128;
    __shared__ float Xs[8][128];
    __shared__ float Ws[8][128];
    int tid = threadIdx.x;
    int tx = tid & 15, ty = tid >> 4;
    int lrow = tid >> 1, lpart = tid & 1;
    int wrow = tid >> 5, wcol = tid & 31;

    float acc[8][8];
    #pragma unroll
    for (int i = 0; i < 8; i++)
        #pragma unroll
        for (int j = 0; j < 8; j++) acc[i][j] = 0.f;

    for (int c = 0; c < 3; c++) {
        const float* X = (c == 0) ? m0 : (c == 1 ? m1 : sl);
        for (int kk = 0; kk < DD; kk += 8) {
            float4 xv = make_float4(0.f, 0.f, 0.f, 0.f);
            int gr = row0 + lrow;
            if (gr < n) xv = *(const float4*)(X + (size_t)gr * DD + kk + lpart * 4);
            Xs[lpart * 4 + 0][lrow] = xv.x;
            Xs[lpart * 4 + 1][lrow] = xv.y;
            Xs[lpart * 4 + 2][lrow] = xv.z;
            Xs[lpart * 4 + 3][lrow] = xv.w;
            float4 wv = *(const float4*)(W + (size_t)(c * DD + kk + wrow) * DD + wcol * 4);
            *(float4*)&Ws[wrow][wcol * 4] = wv;
            __syncthreads();
            #pragma unroll
            for (int kb = 0; kb < 8; kb++) {
                float a[8], bb[8];
                #pragma unroll
                for (int i = 0; i < 4; i++) {
                    a[i]      = Xs[kb][ty * 4 + i];
                    a[4 + i]  = Xs[kb][64 + ty * 4 + i];
                    bb[i]     = Ws[kb][tx * 4 + i];
                    bb[4 + i] = Ws[kb][64 + tx * 4 + i];
                }
                #pragma unroll
                for (int i = 0; i < 8; i++)
                    #pragma unroll
                    for (int j = 0; j < 8; j++) acc[i][j] += a[i] * bb[j];
            }
            __syncthreads();
        }
    }
    #pragma unroll
    for (int i = 0; i < 8; i++) {
        int r = row0 + ((i < 4) ? (ty * 4 + i) : (64 + ty * 4 + (i - 4)));
        if (r >= n) continue;
        #pragma unroll
        for (int jh = 0; jh < 2; jh++) {
            int c0 = jh ? (64 + tx * 4) : (tx * 4);
            float4 o;
            o.x = acc[i][jh * 4 + 0] + B[c0 + 0];
            o.y = acc[i][jh * 4 + 1] + B[c0 + 1];
            o.z = acc[i][jh * 4 + 2] + B[c0 + 2];
            o.w = acc[i][jh * 4 + 3] + B[c0 + 3];
            *(float4*)(Y + (size_t)r * DD + c0) = o;
        }
    }
}

// ---------------- per-column (over N) stats -----------------------------------
#define CH 256
__global__ void k_colstats(const float* __restrict__ y, float* stats, int n, size_t stride) {
    int k = blockIdx.y;
    int d = threadIdx.x;
    const float* base = y + (size_t)k * stride;
    int r0 = blockIdx.x * CH;
    int r1 = min(r0 + CH, n);
    float s = 0.f, sq = 0.f;
    for (int r = r0; r < r1; r++) {
        float v = base[(size_t)r * DD + d];
        s += v;
        sq += v * v;
    }
    atomicAdd(&stats[k * DD + d], s);
    atomicAdd(&stats[3 * DD + k * DD + d], sq);
}

// ---------------- mixed epilogue: normalize + relu + weighted k-sum -----------
__global__ void k_combine(const float* __restrict__ y, const float* __restrict__ stats,
                          const float* __restrict__ wrow, const float* __restrict__ gg,
                          const float* __restrict__ be, float* __restrict__ out,
                          int n, int accum) {
    int idx = blockIdx.x * blockDim.x + threadIdx.x;
    int total = n * DD;
    if (idx >= total) return;
    int d = idx & (DD - 1);
    float fn = (float)n;
    float acc = 0.f;
    #pragma unroll
    for (int k = 0; k < 3; k++) {
        float mu  = stats[k * DD + d] / fn;
        float var = stats[3 * DD + k * DD + d] / fn - mu * mu;
        float rs  = rsqrtf(var + EPSLN);
        float v = y[(size_t)k * n * DD + idx];
        float t = (v - mu) * rs * gg[k * DD + d] + be[k * DD + d];
        t = fmaxf(t, 0.f);
        acc += wrow[k] * t;
    }
    out[idx] = accum ? (out[idx] + acc) : acc;
}

// ---------------- final column-norm + relu ------------------------------------
__global__ void k_finalnorm(const float* __restrict__ h, const float* __restrict__ stats,
                            const float* __restrict__ gc, const float* __restrict__ bec,
                            float* __restrict__ out, int n) {
    int idx = blockIdx.x * blockDim.x + threadIdx.x;
    int total = n * DD;
    if (idx >= total) return;
    int d = idx & (DD - 1);
    float fn = (float)n;
    float mu  = stats[d] / fn;
    float var = stats[3 * DD + d] / fn - mu * mu;
    float rs  = rsqrtf(var + EPSLN);
    float v = (h[idx] - mu) * rs * gc[d] + bec[d];
    out[idx] = fmaxf(v, 0.f);
}

// ---------------- host orchestration ------------------------------------------
extern "C" void kernel_launch(void* const* d_in, const int* in_sizes, int n_in,
                              void* d_out, int out_size) {
    const float* src_emb = (const float*)d_in[0];
    const float* hr      = (const float*)d_in[1];
    const int*   esrc    = (const int*)d_in[2];
    const int*   edst    = (const int*)d_in[3];
    const float* w_zero  = (const float*)d_in[4];   // (1,3)
    const float* w_first = (const float*)d_in[5];   // (3,3)
    const float* w_mid   = (const float*)d_in[6];   // (2,3)
    const float* w_last  = (const float*)d_in[7];   // (2,3)
    const float* W_zero  = (const float*)d_in[8];
    const float* b_zero  = (const float*)d_in[9];
    const float* g_zero  = (const float*)d_in[10];
    const float* be_zero = (const float*)d_in[11];
    const float* W_first = (const float*)d_in[12];
    const float* b_first = (const float*)d_in[13];
    const float* g_first = (const float*)d_in[14];
    const float* be_first= (const float*)d_in[15];
    const float* W_mid   = (const float*)d_in[16];
    const float* b_mid   = (const float*)d_in[17];
    const float* g_mid   = (const float*)d_in[18];
    const float* be_mid  = (const float*)d_in[19];
    const float* W_last  = (const float*)d_in[20];
    const float* b_last  = (const float*)d_in[21];
    const float* g_last  = (const float*)d_in[22];
    const float* be_last = (const float*)d_in[23];
    const float* W_cat   = (const float*)d_in[24];
    const float* b_cat   = (const float*)d_in[25];
    const float* g_cat   = (const float*)d_in[26];
    const float* be_cat  = (const float*)d_in[27];

    int n = in_sizes[0] / DD;
    int e = in_sizes[2];

    float *yb, *hin, *s0, *s1, *m0, *m1, *sl, *mean, *mx, *stats;
    int *deg, *rowptr, *cursor, *ssrc, *bsums;
    cudaGetSymbolAddress((void**)&yb, g_y);
    cudaGetSymbolAddress((void**)&hin, g_hin);
    cudaGetSymbolAddress((void**)&s0, g_s0);
    cudaGetSymbolAddress((void**)&s1, g_s1);
    cudaGetSymbolAddress((void**)&m0, g_m0);
    cudaGetSymbolAddress((void**)&m1, g_m1);
    cudaGetSymbolAddress((void**)&sl, g_slast);
    cudaGetSymbolAddress((void**)&mean, g_mean);
    cudaGetSymbolAddress((void**)&mx, g_max);
    cudaGetSymbolAddress((void**)&stats, g_stats);
    cudaGetSymbolAddress((void**)&deg, g_deg);
    cudaGetSymbolAddress((void**)&rowptr, g_rowptr);
    cudaGetSymbolAddress((void**)&cursor, g_cursor);
    cudaGetSymbolAddress((void**)&ssrc, g_ssrc);
    cudaGetSymbolAddress((void**)&bsums, g_bsums);

    int total = n * DD;
    size_t ystride = (size_t)n * DD;
    dim3 gemm_grid((n + 127) / 128, 1, 3);
    int cs_gx = (n + CH - 1) / CH;
    int ew_grid = (total + 255) / 256;
    int agg_grid = (n + 7) / 8;             // 8 warps per 256-thread block
    int eb = (e + 255) / 256;
    int nb1024 = (n + 1023) / 1024;

    // ---- CSR build (once per launch; reused by all 5 aggregations) ----
    cudaMemsetAsync(deg, 0, (size_t)n * sizeof(int));
    k_hist<<<eb, 256>>>(edst, deg, e);
    k_scan_block<<<nb1024, 1024>>>(deg, cursor, bsums, n);
    k_scan_sums<<<1, 32>>>(bsums, nb1024);
    k_scan_fin<<<(n + 255) / 256, 256>>>(deg, cursor, bsums, rowptr, cursor, n, e);
    k_scatter<<<eb, 256>>>(esrc, edst, cursor, ssrc, e);

    auto run_mixed = [&](const float* x0, const float* x1, const float* x2,
                         const float* W, const float* B, const float* G, const float* BE,
                         const float* wrow, float* out, int accum) {
        k_gemm128<<<gemm_grid, 256>>>(x0, x1, x2, W, B, yb, n, ystride);
        cudaMemsetAsync(stats, 0, 2 * 3 * DD * sizeof(float));
        k_colstats<<<dim3(cs_gx, 3), DD>>>(yb, stats, n, ystride);
        k_combine<<<ew_grid, 256>>>(yb, stats, wrow, G, BE, out, n, accum);
    };

    // ---- zero op: pre candidates -> h_in ----
    k_pre<<<ew_grid, 256>>>(src_emb, hr, mean, mx, total);   // mean=src-hr, mx=src*hr (reuse)
    run_mixed(src_emb, mean, mx, W_zero, b_zero, g_zero, be_zero, w_zero, hin, 0);

    // ---- first ops ----
    k_agg<<<agg_grid, 256>>>(hin, rowptr, ssrc, mean, mx, n);
    run_mixed(hin, mean, mx, W_first + 0 * 3 * DD * DD, b_first + 0 * 3 * DD,
              g_first + 0 * 3 * DD, be_first + 0 * 3 * DD, w_first + 0 * 3, s0, 0);
    run_mixed(hin, mean, mx, W_first + 1 * 3 * DD * DD, b_first + 1 * 3 * DD,
              g_first + 1 * 3 * DD, be_first + 1 * 3 * DD, w_first + 1 * 3, s1, 0);
    k_agg<<<agg_grid, 256>>>(s0, rowptr, ssrc, mean, mx, n);
    run_mixed(s0, mean, mx, W_first + 2 * 3 * DD * DD, b_first + 2 * 3 * DD,
              g_first + 2 * 3 * DD, be_first + 2 * 3 * DD, w_first + 2 * 3, s1, 1);

    // ---- middle ops ----  (agg(s0) still valid in mean/mx)
    run_mixed(s0, mean, mx, W_mid + 0 * 3 * DD * DD, b_mid + 0 * 3 * DD,
              g_mid + 0 * 3 * DD, be_mid + 0 * 3 * DD, w_mid + 0 * 3, m0, 0);
    k_agg<<<agg_grid, 256>>>(s1, rowptr, ssrc, mean, mx, n);
    run_mixed(s1, mean, mx, W_mid + 1 * 3 * DD * DD, b_mid + 1 * 3 * DD,
              g_mid + 1 * 3 * DD, be_mid + 1 * 3 * DD, w_mid + 1 * 3, m1, 0);

    // ---- last ops ----
    k_agg<<<agg_grid, 256>>>(m0, rowptr, ssrc, mean, mx, n);
    run_mixed(m0, mean, mx, W_last + 0 * 3 * DD * DD, b_last + 0 * 3 * DD,
              g_last + 0 * 3 * DD, be_last + 0 * 3 * DD, w_last + 0 * 3, sl, 0);
    k_agg<<<agg_grid, 256>>>(m1, rowptr, ssrc, mean, mx, n);
    run_mixed(m1, mean, mx, W_last + 1 * 3 * DD * DD, b_last + 1 * 3 * DD,
              g_last + 1 * 3 * DD, be_last + 1 * 3 * DD, w_last + 1 * 3, sl, 1);

    // ---- final: hcat = [m0|m1|sl] @ W_cat + b_cat ; column-norm ; relu ----
    k_gemm_cat<<<dim3((n + 127) / 128), 256>>>(m0, m1, sl, W_cat, b_cat, yb, n);
    cudaMemsetAsync(stats, 0, 2 * 3 * DD * sizeof(float));
    k_colstats<<<dim3(cs_gx, 1), DD>>>(yb, stats, n, ystride);
    k_finalnorm<<<ew_grid, 256>>>(yb, stats, g_cat, be_cat, (float*)d_out, n);
}

// round 2
// speedup vs baseline: 1.0525x; 1.0525x over previous
#include <cuda_runtime.h>
#include <cstdint>
#include <math_constants.h>

#define NN 100000
#define EE 600000
#define DD 128
#define EPSLN 1e-5f

// ---------------- scratch (device globals; allocation-free at launch) ----------
__device__ float g_y[3L * NN * DD];
__device__ float g_hin[(size_t)NN * DD];
__device__ float g_s0[(size_t)NN * DD];
__device__ float g_s1[(size_t)NN * DD];
__device__ float g_m0[(size_t)NN * DD];
__device__ float g_m1[(size_t)NN * DD];
__device__ float g_slast[(size_t)NN * DD];
__device__ float g_mean[(size_t)NN * DD];
__device__ float g_max[(size_t)NN * DD];
__device__ float g_stats[2 * 3 * DD];
__device__ int   g_deg[NN];
__device__ int   g_rowptr[NN + 1];
__device__ int   g_cursor[NN];
__device__ int   g_ssrc[EE];
__device__ int   g_bsums[256];

// ---------------- packed f32x2 helpers ----------------------------------------
__device__ __forceinline__ unsigned long long pack2(float lo, float hi) {
    unsigned long long r;
    asm("mov.b64 %0, {%1, %2};" : "=l"(r) : "f"(lo), "f"(hi));
    return r;
}
__device__ __forceinline__ void unpack2(unsigned long long v, float& lo, float& hi) {
    asm("mov.b64 {%0, %1}, %2;" : "=f"(lo), "=f"(hi) : "l"(v));
}
__device__ __forceinline__ unsigned long long fma2(unsigned long long a,
                                                   unsigned long long b,
                                                   unsigned long long c) {
    unsigned long long d;
    asm("fma.rn.f32x2 %0, %1, %2, %3;" : "=l"(d) : "l"(a), "l"(b), "l"(c));
    return d;
}

// ---------------- CSR build ---------------------------------------------------
__global__ void k_hist(const int* __restrict__ dst, int* deg, int e) {
    int i = blockIdx.x * blockDim.x + threadIdx.x;
    if (i < e) atomicAdd(&deg[dst[i]], 1);
}

__global__ void k_scan_block(const int* __restrict__ deg, int* incl, int* bsums, int n) {
    __shared__ int sh[1024];
    int i = blockIdx.x * 1024 + threadIdx.x;
    int v = (i < n) ? deg[i] : 0;
    sh[threadIdx.x] = v;
    __syncthreads();
    for (int off = 1; off < 1024; off <<= 1) {
        int t = (threadIdx.x >= off) ? sh[threadIdx.x - off] : 0;
        __syncthreads();
        sh[threadIdx.x] += t;
        __syncthreads();
    }
    if (i < n) incl[i] = sh[threadIdx.x];
    if (threadIdx.x == 1023) bsums[blockIdx.x] = sh[1023];
}

__global__ void k_scan_sums(int* bsums, int nb) {
    if (threadIdx.x == 0 && blockIdx.x == 0) {
        int run = 0;
        for (int i = 0; i < nb; i++) { int t = bsums[i]; bsums[i] = run; run += t; }
    }
}

__global__ void k_scan_fin(const int* __restrict__ deg, const int* __restrict__ incl,
                           const int* __restrict__ bsums, int* rowptr, int* cursor, int n, int e) {
    int i = blockIdx.x * blockDim.x + threadIdx.x;
    if (i < n) {
        int ex = incl[i] - deg[i] + bsums[i >> 10];
        rowptr[i] = ex;
        cursor[i] = ex;
        if (i == n - 1) rowptr[n] = e;
    }
}

__global__ void k_scatter(const int* __restrict__ src, const int* __restrict__ dst,
                          int* cursor, int* ssrc, int e) {
    int i = blockIdx.x * blockDim.x + threadIdx.x;
    if (i < e) {
        int p = atomicAdd(&cursor[dst[i]], 1);
        ssrc[p] = src[i];
    }
}

// ---------------- graph aggregation (mean + max), warp per node ---------------
__global__ void k_agg(const float* __restrict__ h, const int* __restrict__ rowptr,
                      const int* __restrict__ ssrc, float* __restrict__ meanout,
                      float* __restrict__ maxout, int n) {
    int warp = (blockIdx.x * blockDim.x + threadIdx.x) >> 5;
    int lane = threadIdx.x & 31;
    if (warp >= n) return;
    int beg = rowptr[warp], end = rowptr[warp + 1];
    float4 s  = make_float4(0.f, 0.f, 0.f, 0.f);
    float4 mx = make_float4(-CUDART_INF_F, -CUDART_INF_F, -CUDART_INF_F, -CUDART_INF_F);
    for (int i = beg; i < end; i++) {
        int src = ssrc[i];
        float4 v = ((const float4*)(h + (size_t)src * DD))[lane];
        s.x += v.x; s.y += v.y; s.z += v.z; s.w += v.w;
        mx.x = fmaxf(mx.x, v.x); mx.y = fmaxf(mx.y, v.y);
        mx.z = fmaxf(mx.z, v.z); mx.w = fmaxf(mx.w, v.w);
    }
    int deg = end - beg;
    float inv = 1.0f / (float)max(deg, 1);
    float4 mo = make_float4(s.x * inv, s.y * inv, s.z * inv, s.w * inv);
    float4 xo = (deg > 0) ? mx : make_float4(0.f, 0.f, 0.f, 0.f);
    ((float4*)(meanout + (size_t)warp * DD))[lane] = mo;
    ((float4*)(maxout  + (size_t)warp * DD))[lane] = xo;
}

// ---------------- elementwise pre-candidates ----------------------------------
__global__ void k_pre(const float* __restrict__ a, const float* __restrict__ b,
                      float* __restrict__ p1, float* __restrict__ p2, int total) {
    int i = blockIdx.x * blockDim.x + threadIdx.x;
    if (i < total) {
        float x = a[i], y = b[i];
        p1[i] = x - y;
        p2[i] = x * y;
    }
}

// ---------------- GEMM (FFMA2) + fused column stats ----------------------------
// BM=128, BN=128 (full D), BK=8, 256 threads, 8x8 thread tile via 32 f32x2 accums
__global__ void k_gemm128(const float* __restrict__ x0, const float* __restrict__ x1,
                          const float* __restrict__ x2, const float* __restrict__ W,
                          const float* __restrict__ B, float* __restrict__ Y,
                          float* __restrict__ stats, int n, size_t ystride) {
    int k = blockIdx.z;
    const float* X  = (k == 0) ? x0 : (k == 1 ? x1 : x2);
    const float* Wk = W + (size_t)k * DD * DD;
    const float* bk = B + k * DD;
    float* Yk = Y + (size_t)k * ystride;
    int row0 = blockIdx.x * 128;

    __shared__ float Xs[8][128];
    __shared__ float Ws[8][128];
    __shared__ float ssum[DD];
    __shared__ float ssq[DD];
    int tid = threadIdx.x;
    int tx = tid & 15, ty = tid >> 4;
    int lrow = tid >> 1, lpart = tid & 1;
    int wrow = tid >> 5, wcol = tid & 31;

    if (tid < DD) { ssum[tid] = 0.f; ssq[tid] = 0.f; }

    unsigned long long acc2[8][4];
    #pragma unroll
    for (int i = 0; i < 8; i++)
        #pragma unroll
        for (int j = 0; j < 4; j++) acc2[i][j] = 0ull;

    for (int kk = 0; kk < DD; kk += 8) {
        float4 xv = make_float4(0.f, 0.f, 0.f, 0.f);
        int gr = row0 + lrow;
        if (gr < n) xv = *(const float4*)(X + (size_t)gr * DD + kk + lpart * 4);
        Xs[lpart * 4 + 0][lrow] = xv.x;
        Xs[lpart * 4 + 1][lrow] = xv.y;
        Xs[lpart * 4 + 2][lrow] = xv.z;
        Xs[lpart * 4 + 3][lrow] = xv.w;
        float4 wv = *(const float4*)(Wk + (size_t)(kk + wrow) * DD + wcol * 4);
        *(float4*)&Ws[wrow][wcol * 4] = wv;
        __syncthreads();
        #pragma unroll
        for (int kb = 0; kb < 8; kb++) {
            float4 av0 = *(const float4*)&Xs[kb][ty * 4];
            float4 av1 = *(const float4*)&Xs[kb][64 + ty * 4];
            float4 bv0 = *(const float4*)&Ws[kb][tx * 4];
            float4 bv1 = *(const float4*)&Ws[kb][64 + tx * 4];
            unsigned long long b2[4];
            b2[0] = pack2(bv0.x, bv0.y);
            b2[1] = pack2(bv0.z, bv0.w);
            b2[2] = pack2(bv1.x, bv1.y);
            b2[3] = pack2(bv1.z, bv1.w);
            float a[8] = {av0.x, av0.y, av0.z, av0.w, av1.x, av1.y, av1.z, av1.w};
            #pragma unroll
            for (int i = 0; i < 8; i++) {
                unsigned long long aa = pack2(a[i], a[i]);
                #pragma unroll
                for (int j = 0; j < 4; j++) acc2[i][j] = fma2(aa, b2[j], acc2[i][j]);
            }
        }
        __syncthreads();
    }

    // epilogue: bias add, store, per-thread column partial sums
    float b0[4], b1[4];
    #pragma unroll
    for (int j = 0; j < 4; j++) { b0[j] = bk[tx * 4 + j]; b1[j] = bk[64 + tx * 4 + j]; }
    float csum[8], csq[8];
    #pragma unroll
    for (int j = 0; j < 8; j++) { csum[j] = 0.f; csq[j] = 0.f; }

    #pragma unroll
    for (int i = 0; i < 8; i++) {
        int r = row0 + ((i < 4) ? (ty * 4 + i) : (64 + ty * 4 + (i - 4)));
        if (r >= n) continue;
        float v[8];
        unpack2(acc2[i][0], v[0], v[1]);
        unpack2(acc2[i][1], v[2], v[3]);
        unpack2(acc2[i][2], v[4], v[5]);
        unpack2(acc2[i][3], v[6], v[7]);
        #pragma unroll
        for (int j = 0; j < 4; j++) { v[j] += b0[j]; v[4 + j] += b1[j]; }
        float4 o0 = make_float4(v[0], v[1], v[2], v[3]);
        float4 o1 = make_float4(v[4], v[5], v[6], v[7]);
        *(float4*)(Yk + (size_t)r * DD + tx * 4) = o0;
        *(float4*)(Yk + (size_t)r * DD + 64 + tx * 4) = o1;
        #pragma unroll
        for (int j = 0; j < 8; j++) { csum[j] += v[j]; csq[j] += v[j] * v[j]; }
    }
    __syncthreads();
    #pragma unroll
    for (int j = 0; j < 4; j++) {
        atomicAdd(&ssum[tx * 4 + j], csum[j]);
        atomicAdd(&ssq[tx * 4 + j], csq[j]);
        atomicAdd(&ssum[64 + tx * 4 + j], csum[4 + j]);
        atomicAdd(&ssq[64 + tx * 4 + j], csq[4 + j]);
    }
    __syncthreads();
    if (tid < DD) {
        atomicAdd(&stats[k * DD + tid], ssum[tid]);
        atomicAdd(&stats[3 * DD + k * DD + tid], ssq[tid]);
    }
}

// ---------------- GEMM cat (FFMA2, K=384) + fused column stats -----------------
__global__ void k_gemm_cat(const float* __restrict__ m0, const float* __restrict__ m1,
                           const float* __restrict__ sl, const float* __restrict__ W,
                           const float* __restrict__ B, float* __restrict__ Y,
                           float* __restrict__ stats, int n) {
    int row0 = blockIdx.x * 128;
    __shared__ float Xs[8][128];
    __shared__ float Ws[8][128];
    __shared__ float ssum[DD];
    __shared__ float ssq[DD];
    int tid = threadIdx.x;
    int tx = tid & 15, ty = tid >> 4;
    int lrow = tid >> 1, lpart = tid & 1;
    int wrow = tid >> 5, wcol = tid & 31;

    if (tid < DD) { ssum[tid] = 0.f; ssq[tid] = 0.f; }

    unsigned long long acc2[8][4];
    #pragma unroll
    for (int i = 0; i < 8; i++)
        #pragma unroll
        for (int j = 0; j < 4; j++) acc2[i][j] = 0ull;

    for (int c = 0; c < 3; c++) {
        const float* X = (c == 0) ? m0 : (c == 1 ? m1 : sl);
        for (int kk = 0; kk < DD; kk += 8) {
            float4 xv = make_float4(0.f, 0.f, 0.f, 0.f);
            int gr = row0 + lrow;
            if (gr < n) xv = *(const float4*)(X + (size_t)gr * DD + kk + lpart * 4);
            Xs[lpart * 4 + 0][lrow] = xv.x;
            Xs[lpart * 4 + 1][lrow] = xv.y;
            Xs[lpart * 4 + 2][lrow] = xv.z;
            Xs[lpart * 4 + 3][lrow] = xv.w;
            float4 wv = *(const float4*)(W + (size_t)(c * DD + kk + wrow) * DD + wcol * 4);
            *(float4*)&Ws[wrow][wcol * 4] = wv;
            __syncthreads();
            #pragma unroll
            for (int kb = 0; kb < 8; kb++) {
                float4 av0 = *(const float4*)&Xs[kb][ty * 4];
                float4 av1 = *(const float4*)&Xs[kb][64 + ty * 4];
                float4 bv0 = *(const float4*)&Ws[kb][tx * 4];
                float4 bv1 = *(const float4*)&Ws[kb][64 + tx * 4];
                unsigned long long b2[4];
                b2[0] = pack2(bv0.x, bv0.y);
                b2[1] = pack2(bv0.z, bv0.w);
                b2[2] = pack2(bv1.x, bv1.y);
                b2[3] = pack2(bv1.z, bv1.w);
                float a[8] = {av0.x, av0.y, av0.z, av0.w, av1.x, av1.y, av1.z, av1.w};
                #pragma unroll
                for (int i = 0; i < 8; i++) {
                    unsigned long long aa = pack2(a[i], a[i]);
                    #pragma unroll
                    for (int j = 0; j < 4; j++) acc2[i][j] = fma2(aa, b2[j], acc2[i][j]);
                }
            }
            __syncthreads();
        }
    }

    float b0[4], b1[4];
    #pragma unroll
    for (int j = 0; j < 4; j++) { b0[j] = B[tx * 4 + j]; b1[j] = B[64 + tx * 4 + j]; }
    float csum[8], csq[8];
    #pragma unroll
    for (int j = 0; j < 8; j++) { csum[j] = 0.f; csq[j] = 0.f; }

    #pragma unroll
    for (int i = 0; i < 8; i++) {
        int r = row0 + ((i < 4) ? (ty * 4 + i) : (64 + ty * 4 + (i - 4)));
        if (r >= n) continue;
        float v[8];
        unpack2(acc2[i][0], v[0], v[1]);
        unpack2(acc2[i][1], v[2], v[3]);
        unpack2(acc2[i][2], v[4], v[5]);
        unpack2(acc2[i][3], v[6], v[7]);
        #pragma unroll
        for (int j = 0; j < 4; j++) { v[j] += b0[j]; v[4 + j] += b1[j]; }
        *(float4*)(Y + (size_t)r * DD + tx * 4) = make_float4(v[0], v[1], v[2], v[3]);
        *(float4*)(Y + (size_t)r * DD + 64 + tx * 4) = make_float4(v[4], v[5], v[6], v[7]);
        #pragma unroll
        for (int j = 0; j < 8; j++) { csum[j] += v[j]; csq[j] += v[j] * v[j]; }
    }
    __syncthreads();
    #pragma unroll
    for (int j = 0; j < 4; j++) {
        atomicAdd(&ssum[tx * 4 + j], csum[j]);
        atomicAdd(&ssq[tx * 4 + j], csq[j]);
        atomicAdd(&ssum[64 + tx * 4 + j], csum[4 + j]);
        atomicAdd(&ssq[64 + tx * 4 + j], csq[4 + j]);
    }
    __syncthreads();
    if (tid < DD) {
        atomicAdd(&stats[tid], ssum[tid]);
        atomicAdd(&stats[3 * DD + tid], ssq[tid]);
    }
}

// ---------------- mixed epilogue: normalize + relu + weighted k-sum -----------
__global__ void k_combine(const float* __restrict__ y, const float* __restrict__ stats,
                          const float* __restrict__ wrow, const float* __restrict__ gg,
                          const float* __restrict__ be, float* __restrict__ out,
                          int n, int accum) {
    int idx = blockIdx.x * blockDim.x + threadIdx.x;
    int total = n * DD;
    if (idx >= total) return;
    int d = idx & (DD - 1);
    float fn = (float)n;
    float acc = 0.f;
    #pragma unroll
    for (int k = 0; k < 3; k++) {
        float mu  = stats[k * DD + d] / fn;
        float var = stats[3 * DD + k * DD + d] / fn - mu * mu;
        float rs  = rsqrtf(var + EPSLN);
        float v = y[(size_t)k * n * DD + idx];
        float t = (v - mu) * rs * gg[k * DD + d] + be[k * DD + d];
        t = fmaxf(t, 0.f);
        acc += wrow[k] * t;
    }
    out[idx] = accum ? (out[idx] + acc) : acc;
}

// ---------------- final column-norm + relu ------------------------------------
__global__ void k_finalnorm(const float* __restrict__ h, const float* __restrict__ stats,
                            const float* __restrict__ gc, const float* __restrict__ bec,
                            float* __restrict__ out, int n) {
    int idx = blockIdx.x * blockDim.x + threadIdx.x;
    int total = n * DD;
    if (idx >= total) return;
    int d = idx & (DD - 1);
    float fn = (float)n;
    float mu  = stats[d] / fn;
    float var = stats[3 * DD + d] / fn - mu * mu;
    float rs  = rsqrtf(var + EPSLN);
    float v = (h[idx] - mu) * rs * gc[d] + bec[d];
    out[idx] = fmaxf(v, 0.f);
}

// ---------------- host orchestration ------------------------------------------
extern "C" void kernel_launch(void* const* d_in, const int* in_sizes, int n_in,
                              void* d_out, int out_size) {
    const float* src_emb = (const float*)d_in[0];
    const float* hr      = (const float*)d_in[1];
    const int*   esrc    = (const int*)d_in[2];
    const int*   edst    = (const int*)d_in[3];
    const float* w_zero  = (const float*)d_in[4];
    const float* w_first = (const float*)d_in[5];
    const float* w_mid   = (const float*)d_in[6];
    const float* w_last  = (const float*)d_in[7];
    const float* W_zero  = (const float*)d_in[8];
    const float* b_zero  = (const float*)d_in[9];
    const float* g_zero  = (const float*)d_in[10];
    const float* be_zero = (const float*)d_in[11];
    const float* W_first = (const float*)d_in[12];
    const float* b_first = (const float*)d_in[13];
    const float* g_first = (const float*)d_in[14];
    const float* be_first= (const float*)d_in[15];
    const float* W_mid   = (const float*)d_in[16];
    const float* b_mid   = (const float*)d_in[17];
    const float* g_mid   = (const float*)d_in[18];
    const float* be_mid  = (const float*)d_in[19];
    const float* W_last  = (const float*)d_in[20];
    const float* b_last  = (const float*)d_in[21];
    const float* g_last  = (const float*)d_in[22];
    const float* be_last = (const float*)d_in[23];
    const float* W_cat   = (const float*)d_in[24];
    const float* b_cat   = (const float*)d_in[25];
    const float* g_cat   = (const float*)d_in[26];
    const float* be_cat  = (const float*)d_in[27];

    int n = in_sizes[0] / DD;
    int e = in_sizes[2];

    float *yb, *hin, *s0, *s1, *m0, *m1, *sl, *mean, *mx, *stats;
    int *deg, *rowptr, *cursor, *ssrc, *bsums;
    cudaGetSymbolAddress((void**)&yb, g_y);
    cudaGetSymbolAddress((void**)&hin, g_hin);
    cudaGetSymbolAddress((void**)&s0, g_s0);
    cudaGetSymbolAddress((void**)&s1, g_s1);
    cudaGetSymbolAddress((void**)&m0, g_m0);
    cudaGetSymbolAddress((void**)&m1, g_m1);
    cudaGetSymbolAddress((void**)&sl, g_slast);
    cudaGetSymbolAddress((void**)&mean, g_mean);
    cudaGetSymbolAddress((void**)&mx, g_max);
    cudaGetSymbolAddress((void**)&stats, g_stats);
    cudaGetSymbolAddress((void**)&deg, g_deg);
    cudaGetSymbolAddress((void**)&rowptr, g_rowptr);
    cudaGetSymbolAddress((void**)&cursor, g_cursor);
    cudaGetSymbolAddress((void**)&ssrc, g_ssrc);
    cudaGetSymbolAddress((void**)&bsums, g_bsums);

    int total = n * DD;
    size_t ystride = (size_t)n * DD;
    dim3 gemm_grid((n + 127) / 128, 1, 3);
    int ew_grid = (total + 255) / 256;
    int agg_grid = (n + 7) / 8;
    int eb = (e + 255) / 256;
    int nb1024 = (n + 1023) / 1024;

    // ---- CSR build ----
    cudaMemsetAsync(deg, 0, (size_t)n * sizeof(int));
    k_hist<<<eb, 256>>>(edst, deg, e);
    k_scan_block<<<nb1024, 1024>>>(deg, cursor, bsums, n);
    k_scan_sums<<<1, 32>>>(bsums, nb1024);
    k_scan_fin<<<(n + 255) / 256, 256>>>(deg, cursor, bsums, rowptr, cursor, n, e);
    k_scatter<<<eb, 256>>>(esrc, edst, cursor, ssrc, e);

    auto run_mixed = [&](const float* x0, const float* x1, const float* x2,
                         const float* W, const float* B, const float* G, const float* BE,
                         const float* wrow, float* out, int accum) {
        cudaMemsetAsync(stats, 0, 2 * 3 * DD * sizeof(float));
        k_gemm128<<<gemm_grid, 256>>>(x0, x1, x2, W, B, yb, stats, n, ystride);
        k_combine<<<ew_grid, 256>>>(yb, stats, wrow, G, BE, out, n, accum);
    };

    // ---- zero op ----
    k_pre<<<ew_grid, 256>>>(src_emb, hr, mean, mx, total);
    run_mixed(src_emb, mean, mx, W_zero, b_zero, g_zero, be_zero, w_zero, hin, 0);

    // ---- first ops ----
    k_agg<<<agg_grid, 256>>>(hin, rowptr, ssrc, mean, mx, n);
    run_mixed(hin, mean, mx, W_first + 0 * 3 * DD * DD, b_first + 0 * 3 * DD,
              g_first + 0 * 3 * DD, be_first + 0 * 3 * DD, w_first + 0 * 3, s0, 0);
    run_mixed(hin, mean, mx, W_first + 1 * 3 * DD * DD, b_first + 1 * 3 * DD,
              g_first + 1 * 3 * DD, be_first + 1 * 3 * DD, w_first + 1 * 3, s1, 0);
    k_agg<<<agg_grid, 256>>>(s0, rowptr, ssrc, mean, mx, n);
    run_mixed(s0, mean, mx, W_first + 2 * 3 * DD * DD, b_first + 2 * 3 * DD,
              g_first + 2 * 3 * DD, be_first + 2 * 3 * DD, w_first + 2 * 3, s1, 1);

    // ---- middle ops ----
    run_mixed(s0, mean, mx, W_mid + 0 * 3 * DD * DD, b_mid + 0 * 3 * DD,
              g_mid + 0 * 3 * DD, be_mid + 0 * 3 * DD, w_mid + 0 * 3, m0, 0);
    k_agg<<<agg_grid, 256>>>(s1, rowptr, ssrc, mean, mx, n);
    run_mixed(s1, mean, mx, W_mid + 1 * 3 * DD * DD, b_mid + 1 * 3 * DD,
              g_mid + 1 * 3 * DD, be_mid + 1 * 3 * DD, w_mid + 1 * 3, m1, 0);

    // ---- last ops ----
    k_agg<<<agg_grid, 256>>>(m0, rowptr, ssrc, mean, mx, n);
    run_mixed(m0, mean, mx, W_last + 0 * 3 * DD * DD, b_last + 0 * 3 * DD,
              g_last + 0 * 3 * DD, be_last + 0 * 3 * DD, w_last + 0 * 3, sl, 0);
    k_agg<<<agg_grid, 256>>>(m1, rowptr, ssrc, mean, mx, n);
    run_mixed(m1, mean, mx, W_last + 1 * 3 * DD * DD, b_last + 1 * 3 * DD,
              g_last + 1 * 3 * DD, be_last + 1 * 3 * DD, w_last + 1 * 3, sl, 1);

    // ---- final cat GEMM + column-norm ----
    cudaMemsetAsync(stats, 0, 2 * 3 * DD * sizeof(float));
    k_gemm_cat<<<dim3((n + 127) / 128), 256>>>(m0, m1, sl, W_cat, b_cat, yb, stats, n);
    k_finalnorm<<<ew_grid, 256>>>(yb, stats, g_cat, be_cat, (float*)d_out, n);
}